// round 7
// baseline (speedup 1.0000x reference)
#include <cuda_runtime.h>
#include <math.h>

#define BB 4096
#define TT 200
#define DD 64
#define H1 80
#define H2 40
#define NEG_BIG_F (-4294967295.0f)
#define S1S 84   // S1 row stride in floats
#define KSS 10   // K chunk row stride in floats (8 data + 2 pad; 2-way max conflict)

typedef unsigned long long u64;

__device__ __forceinline__ u64 pack2(float lo, float hi) {
    u64 r; asm("mov.b64 %0, {%1, %2};" : "=l"(r) : "f"(lo), "f"(hi)); return r;
}
__device__ __forceinline__ void unpack2(u64 v, float& lo, float& hi) {
    asm("mov.b64 {%0, %1}, %2;" : "=f"(lo), "=f"(hi) : "l"(v));
}
__device__ __forceinline__ void fma2(u64& d, u64 a, u64 b) {
    asm("fma.rn.f32x2 %0, %1, %2, %0;" : "+l"(d) : "l"(a), "l"(b));
}

__device__ __forceinline__ void relu_store8(const u64* a, float* dst) {
    float x0,x1,x2,x3,x4,x5,x6,x7;
    unpack2(a[0],x0,x1); unpack2(a[1],x2,x3);
    unpack2(a[2],x4,x5); unpack2(a[3],x6,x7);
    ((float4*)dst)[0] = make_float4(fmaxf(x0,0.f),fmaxf(x1,0.f),fmaxf(x2,0.f),fmaxf(x3,0.f));
    ((float4*)dst)[1] = make_float4(fmaxf(x4,0.f),fmaxf(x5,0.f),fmaxf(x6,0.f),fmaxf(x7,0.f));
}

__device__ __forceinline__ float relu_dot8(const u64* a, const float* wf) {
    float x0,x1,x2,x3,x4,x5,x6,x7;
    unpack2(a[0],x0,x1); unpack2(a[1],x2,x3);
    unpack2(a[2],x4,x5); unpack2(a[3],x6,x7);
    float s = fmaxf(x0,0.f)*wf[0];
    s = fmaf(fmaxf(x1,0.f), wf[1], s);
    s = fmaf(fmaxf(x2,0.f), wf[2], s);
    s = fmaf(fmaxf(x3,0.f), wf[3], s);
    s = fmaf(fmaxf(x4,0.f), wf[4], s);
    s = fmaf(fmaxf(x5,0.f), wf[5], s);
    s = fmaf(fmaxf(x6,0.f), wf[6], s);
    s = fmaf(fmaxf(x7,0.f), wf[7], s);
    return s;
}

// smem float offsets (U region: K-chunk staging in GEMM1, p2 partials afterwards)
#define OFF_Q      0
#define OFF_WK     (OFF_Q + 64)           // Wk transposed [64][80]
#define OFF_C      (OFF_WK + 64*80)       // [80]
#define OFF_W2     (OFF_C + 80)           // [80][40]
#define OFF_B2     (OFF_W2 + 80*40)       // [40]
#define OFF_WF     (OFF_B2 + 40)          // [40]
#define OFF_S1     (OFF_WF + 40)          // [200][S1S]
#define OFF_U      (OFF_S1 + 200*S1S)     // max(200*KSS, 1000) = 2000
#define OFF_SC     (OFF_U + 2000)         // [200]
#define OFF_RED    (OFF_SC + 200)         // [8]
#define OFF_PART   (OFF_RED + 8)          // [256]
#define OFF_MXINV  (OFF_PART + 256)       // [2]
#define SMEM_FLOATS (OFF_MXINV + 2)

__global__ __launch_bounds__(256, 2)
void din_attn_kernel(const float* __restrict__ q, const float* __restrict__ kin,
                     const float* __restrict__ v, const int* __restrict__ mask,
                     const float* __restrict__ W1, const float* __restrict__ b1,
                     const float* __restrict__ W2, const float* __restrict__ b2,
                     const float* __restrict__ Wf, const float* __restrict__ bf,
                     float* __restrict__ out)
{
    extern __shared__ float sm[];
    float* q_sh = sm + OFF_Q;
    float* Wk   = sm + OFF_WK;
    float* c_sh = sm + OFF_C;
    float* W2s  = sm + OFF_W2;
    float* b2s  = sm + OFF_B2;
    float* Wfs  = sm + OFF_WF;
    float* S1   = sm + OFF_S1;
    float* Ksh  = sm + OFF_U;             // [200][KSS] during GEMM1
    float* p2   = sm + OFF_U;             // [200*5] during GEMM2+
    float* sc   = sm + OFF_SC;
    float* red  = sm + OFF_RED;
    float* part = sm + OFF_PART;
    float* mxin = sm + OFF_MXINV;

    const int tid = threadIdx.x;
    const int b   = blockIdx.x;

    if (tid < DD) q_sh[tid] = q[b * DD + tid];
    __syncthreads();

    // ---- fold W1 into Wk^T [i][j] + bias c ----
    for (int idx = tid; idx < DD * H1; idx += 256) {
        int i = idx / H1;
        int j = idx - i * H1;
        Wk[i * H1 + j] = W1[(64 + i) * H1 + j]
                       - W1[(128 + i) * H1 + j]
                       + q_sh[i] * W1[(192 + i) * H1 + j];
    }
    for (int idx = tid; idx < H1 * H2; idx += 256) W2s[idx] = W2[idx];
    if (tid < H2) { b2s[tid] = b2[tid]; Wfs[tid] = Wf[tid]; }
    if (tid < H1) {
        float acc = b1[tid];
        #pragma unroll 8
        for (int i = 0; i < DD; i++)
            acc += q_sh[i] * (W1[i * H1 + tid] + W1[(128 + i) * H1 + tid]);
        c_sh[tid] = acc;
    }
    __syncthreads();

    // ---- GEMM1: S1[200][80] = relu(c + K @ Wk^T), 8tok x 8j tiles,
    //      K staged through shared in 8 chunks of 8 i's ----
    const int tg = tid / 10;          // 0..24 (for tid<250)
    const int jg = tid - tg * 10;     // 0..9
    const int jc = jg * 8;

    u64 acc1[8][4];
    if (tid < 250) {
        u64 c0 = pack2(c_sh[jc],     c_sh[jc + 1]);
        u64 c1 = pack2(c_sh[jc + 2], c_sh[jc + 3]);
        u64 c2 = pack2(c_sh[jc + 4], c_sh[jc + 5]);
        u64 c3 = pack2(c_sh[jc + 6], c_sh[jc + 7]);
        #pragma unroll
        for (int tt = 0; tt < 8; tt++) {
            acc1[tt][0] = c0; acc1[tt][1] = c1; acc1[tt][2] = c2; acc1[tt][3] = c3;
        }
    }

    #pragma unroll 1
    for (int ic = 0; ic < 8; ic++) {
        // cooperative prefetch of K[:,ic*8 .. ic*8+8) : 400 float4 loads
        #pragma unroll
        for (int r = 0; r < 2; r++) {
            int idx = tid + r * 256;
            if (idx < 400) {
                int row  = idx >> 1;
                int half = idx & 1;
                float4 kv = *(const float4*)(kin + ((size_t)b * TT + row) * DD + ic * 8 + half * 4);
                float* dst = Ksh + row * KSS + half * 4;
                *(float2*)dst       = make_float2(kv.x, kv.y);
                *(float2*)(dst + 2) = make_float2(kv.z, kv.w);
            }
        }
        __syncthreads();

        if (tid < 250) {
            const float* kr = Ksh + tg * 8 * KSS;
            #pragma unroll
            for (int i2 = 0; i2 < 8; i2 += 2) {
                const int i = ic * 8 + i2;
                const ulonglong2* wr0 = (const ulonglong2*)(Wk + i * H1 + jc);
                const ulonglong2* wr1 = (const ulonglong2*)(Wk + (i + 1) * H1 + jc);
                ulonglong2 wA0 = wr0[0];
                ulonglong2 wB0 = wr0[1];
                ulonglong2 wA1 = wr1[0];
                ulonglong2 wB1 = wr1[1];
                #pragma unroll
                for (int tt = 0; tt < 8; tt++) {
                    float2 kv = *(const float2*)(kr + tt * KSS + i2);
                    u64 s0 = pack2(kv.x, kv.x);
                    u64 s1 = pack2(kv.y, kv.y);
                    fma2(acc1[tt][0], s0, wA0.x);
                    fma2(acc1[tt][1], s0, wA0.y);
                    fma2(acc1[tt][2], s0, wB0.x);
                    fma2(acc1[tt][3], s0, wB0.y);
                    fma2(acc1[tt][0], s1, wA1.x);
                    fma2(acc1[tt][1], s1, wA1.y);
                    fma2(acc1[tt][2], s1, wB1.x);
                    fma2(acc1[tt][3], s1, wB1.y);
                }
            }
        }
        __syncthreads();
    }
    if (tid < 250) {
        #pragma unroll
        for (int tt = 0; tt < 8; tt++)
            relu_store8(acc1[tt], S1 + (tg * 8 + tt) * S1S + jc);
    }
    __syncthreads();

    // ---- GEMM2: S2[200][40] = relu(b2 + S1 @ W2), 4tok x 8g tiles; fold Wf ----
    if (tid < 250) {
        const int tg2 = tid / 5;
        const int gg  = tid - tg2 * 5;
        const int gc  = gg * 8;
        const float* s1b = S1 + (size_t)(tg2 * 4) * S1S;

        u64 acc[4][4];
        {
            u64 c0 = pack2(b2s[gc],     b2s[gc + 1]);
            u64 c1 = pack2(b2s[gc + 2], b2s[gc + 3]);
            u64 c2 = pack2(b2s[gc + 4], b2s[gc + 5]);
            u64 c3 = pack2(b2s[gc + 6], b2s[gc + 7]);
            #pragma unroll
            for (int tt = 0; tt < 4; tt++) {
                acc[tt][0] = c0; acc[tt][1] = c1; acc[tt][2] = c2; acc[tt][3] = c3;
            }
        }

        #pragma unroll 2
        for (int j = 0; j < H1; j += 4) {
            float sr[4][4];
            *(float4*)sr[0] = *(const float4*)(s1b + 0 * S1S + j);
            *(float4*)sr[1] = *(const float4*)(s1b + 1 * S1S + j);
            *(float4*)sr[2] = *(const float4*)(s1b + 2 * S1S + j);
            *(float4*)sr[3] = *(const float4*)(s1b + 3 * S1S + j);
            #pragma unroll
            for (int ji = 0; ji < 4; ji++) {
                const ulonglong2* wr = (const ulonglong2*)(W2s + (j + ji) * H2 + gc);
                ulonglong2 wA = wr[0];
                ulonglong2 wB = wr[1];
                #pragma unroll
                for (int tt = 0; tt < 4; tt++) {
                    u64 s = pack2(sr[tt][ji], sr[tt][ji]);
                    fma2(acc[tt][0], s, wA.x);
                    fma2(acc[tt][1], s, wA.y);
                    fma2(acc[tt][2], s, wB.x);
                    fma2(acc[tt][3], s, wB.y);
                }
            }
        }
        float wf[8];
        *(float4*)wf       = *(const float4*)(Wfs + gc);
        *(float4*)(wf + 4) = *(const float4*)(Wfs + gc + 4);
        #pragma unroll
        for (int tt = 0; tt < 4; tt++)
            p2[(tg2 * 4 + tt) * 5 + gg] = relu_dot8(acc[tt], wf);
    }
    __syncthreads();

    // ---- score assembly + softmax ----
    if (tid < TT) {
        float s = bf[0] + ((p2[tid * 5] + p2[tid * 5 + 1]) +
                           (p2[tid * 5 + 2] + p2[tid * 5 + 3]) + p2[tid * 5 + 4]);
        if (mask[(size_t)b * TT + tid] == 0) s = NEG_BIG_F;
        sc[tid] = s;
    }
    __syncthreads();

    float mval = (tid < TT) ? sc[tid] : -3.0e38f;
    #pragma unroll
    for (int o = 16; o; o >>= 1)
        mval = fmaxf(mval, __shfl_xor_sync(0xffffffffu, mval, o));
    if ((tid & 31) == 0) red[tid >> 5] = mval;
    __syncthreads();
    if (tid == 0) {
        float m = red[0];
        #pragma unroll
        for (int w = 1; w < 8; w++) m = fmaxf(m, red[w]);
        mxin[0] = m;
    }
    __syncthreads();
    const float mx = mxin[0];
    float e = (tid < TT) ? __expf(sc[tid] - mx) : 0.0f;
    if (tid < TT) sc[tid] = e;
    float sval = e;
    #pragma unroll
    for (int o = 16; o; o >>= 1)
        sval += __shfl_xor_sync(0xffffffffu, sval, o);
    if ((tid & 31) == 0) red[tid >> 5] = sval;
    __syncthreads();
    if (tid == 0) {
        float smv = 0.0f;
        #pragma unroll
        for (int w = 0; w < 8; w++) smv += red[w];
        mxin[1] = 1.0f / smv;
    }
    __syncthreads();

    // ---- out = attn @ V ----
    const float inv = mxin[1];
    const int dd = tid & 63;
    const int p  = tid >> 6;
    const float* vb = v + (size_t)b * TT * DD;
    float a0 = 0.f, a1 = 0.f;
    const int t0 = p * 50;
    #pragma unroll 5
    for (int t = t0; t < t0 + 50; t += 2) {
        a0 = fmaf(sc[t],     vb[(size_t)t * DD + dd],       a0);
        a1 = fmaf(sc[t + 1], vb[(size_t)(t + 1) * DD + dd], a1);
    }
    part[tid] = a0 + a1;
    __syncthreads();
    if (tid < DD) {
        float r = part[tid] + part[tid + 64] + part[tid + 128] + part[tid + 192];
        out[(size_t)b * DD + tid] = r * inv;
    }
}

extern "C" void kernel_launch(void* const* d_in, const int* in_sizes, int n_in,
                              void* d_out, int out_size)
{
    const float* q    = (const float*)d_in[0];
    const float* k    = (const float*)d_in[1];
    const float* v    = (const float*)d_in[2];
    const int*   mask = (const int*)  d_in[3];
    const float* W1   = (const float*)d_in[4];
    const float* b1   = (const float*)d_in[5];
    const float* W2   = (const float*)d_in[6];
    const float* b2   = (const float*)d_in[7];
    const float* Wf   = (const float*)d_in[8];
    const float* bf   = (const float*)d_in[9];
    float* out = (float*)d_out;

    const int smem_bytes = SMEM_FLOATS * (int)sizeof(float);
    cudaFuncSetAttribute(din_attn_kernel,
                         cudaFuncAttributeMaxDynamicSharedMemorySize, smem_bytes);
    din_attn_kernel<<<BB, 256, smem_bytes>>>(q, k, v, mask, W1, b1, W2, b2, Wf, bf, out);
}

// round 8
// speedup vs baseline: 1.6545x; 1.6545x over previous
#include <cuda_runtime.h>
#include <math.h>

#define BB 4096
#define TT 200
#define DD 64
#define H1 80
#define H2 40
#define NEG_BIG_F (-4294967295.0f)
#define S1S 84   // S1 row stride in floats

typedef unsigned long long u64;

__device__ __forceinline__ u64 pack2(float lo, float hi) {
    u64 r; asm("mov.b64 %0, {%1, %2};" : "=l"(r) : "f"(lo), "f"(hi)); return r;
}
__device__ __forceinline__ void unpack2(u64 v, float& lo, float& hi) {
    asm("mov.b64 {%0, %1}, %2;" : "=f"(lo), "=f"(hi) : "l"(v));
}
__device__ __forceinline__ void fma2(u64& d, u64 a, u64 b) {
    asm("fma.rn.f32x2 %0, %1, %2, %0;" : "+l"(d) : "l"(a), "l"(b));
}

__device__ __forceinline__ void relu_store8(const u64* a, float* dst) {
    float x0,x1,x2,x3,x4,x5,x6,x7;
    unpack2(a[0],x0,x1); unpack2(a[1],x2,x3);
    unpack2(a[2],x4,x5); unpack2(a[3],x6,x7);
    ((float4*)dst)[0] = make_float4(fmaxf(x0,0.f),fmaxf(x1,0.f),fmaxf(x2,0.f),fmaxf(x3,0.f));
    ((float4*)dst)[1] = make_float4(fmaxf(x4,0.f),fmaxf(x5,0.f),fmaxf(x6,0.f),fmaxf(x7,0.f));
}

__device__ __forceinline__ float relu_dot8(const u64* a, const float* wf) {
    float x0,x1,x2,x3,x4,x5,x6,x7;
    unpack2(a[0],x0,x1); unpack2(a[1],x2,x3);
    unpack2(a[2],x4,x5); unpack2(a[3],x6,x7);
    float s = fmaxf(x0,0.f)*wf[0];
    s = fmaf(fmaxf(x1,0.f), wf[1], s);
    s = fmaf(fmaxf(x2,0.f), wf[2], s);
    s = fmaf(fmaxf(x3,0.f), wf[3], s);
    s = fmaf(fmaxf(x4,0.f), wf[4], s);
    s = fmaf(fmaxf(x5,0.f), wf[5], s);
    s = fmaf(fmaxf(x6,0.f), wf[6], s);
    s = fmaf(fmaxf(x7,0.f), wf[7], s);
    return s;
}

// smem float offsets
#define OFF_Q      0
#define OFF_WK     (OFF_Q + 64)           // Wk transposed [64][80]
#define OFF_C      (OFF_WK + 64*80)       // [80]
#define OFF_W2     (OFF_C + 80)           // [80][40]
#define OFF_B2     (OFF_W2 + 80*40)       // [40]
#define OFF_WF     (OFF_B2 + 40)          // [40]
#define OFF_S1     (OFF_WF + 40)          // [200][S1S]
#define OFF_P2     (OFF_S1 + 200*S1S)     // [200*5]
#define OFF_SC     (OFF_P2 + 1000)        // [200]
#define OFF_RED    (OFF_SC + 200)         // [8]
#define OFF_PART   (OFF_RED + 8)          // [256]
#define OFF_MXINV  (OFF_PART + 256)       // [2]
#define SMEM_FLOATS (OFF_MXINV + 2)

__global__ __launch_bounds__(256, 2)
void din_attn_kernel(const float* __restrict__ q, const float* __restrict__ kin,
                     const float* __restrict__ v, const int* __restrict__ mask,
                     const float* __restrict__ W1, const float* __restrict__ b1,
                     const float* __restrict__ W2, const float* __restrict__ b2,
                     const float* __restrict__ Wf, const float* __restrict__ bf,
                     float* __restrict__ out)
{
    extern __shared__ float sm[];
    float* q_sh = sm + OFF_Q;
    float* Wk   = sm + OFF_WK;
    float* c_sh = sm + OFF_C;
    float* W2s  = sm + OFF_W2;
    float* b2s  = sm + OFF_B2;
    float* Wfs  = sm + OFF_WF;
    float* S1   = sm + OFF_S1;
    float* p2   = sm + OFF_P2;
    float* sc   = sm + OFF_SC;
    float* red  = sm + OFF_RED;
    float* part = sm + OFF_PART;
    float* mxin = sm + OFF_MXINV;

    const int tid = threadIdx.x;
    const int b   = blockIdx.x;

    // GEMM1 tile coords (valid for tid<250)
    const int tg = tid / 10;
    const int jg = tid - tg * 10;
    const int jc = jg * 8;
    const float* kb = kin + ((size_t)b * TT + tg * 8) * DD;

    // ---- hoisted prefetch of first K chunk (overlaps entire fold phase) ----
    float2 kv[8];
    if (tid < 250) {
        #pragma unroll
        for (int tt = 0; tt < 8; tt++) kv[tt] = *(const float2*)(kb + tt * DD);
    }

    if (tid < DD) q_sh[tid] = q[b * DD + tid];
    __syncthreads();

    // ---- fold W1 into Wk^T [i][j] + bias c ----
    for (int idx = tid; idx < DD * H1; idx += 256) {
        int i = idx / H1;
        int j = idx - i * H1;
        Wk[i * H1 + j] = W1[(64 + i) * H1 + j]
                       - W1[(128 + i) * H1 + j]
                       + q_sh[i] * W1[(192 + i) * H1 + j];
    }
    for (int idx = tid; idx < H1 * H2; idx += 256) W2s[idx] = W2[idx];
    if (tid < H2) { b2s[tid] = b2[tid]; Wfs[tid] = Wf[tid]; }
    if (tid < H1) {
        float acc = b1[tid];
        #pragma unroll 8
        for (int i = 0; i < DD; i++)
            acc += q_sh[i] * (W1[i * H1 + tid] + W1[(128 + i) * H1 + tid]);
        c_sh[tid] = acc;
    }
    __syncthreads();

    // ---- GEMM1: S1[200][80] = relu(c + K @ Wk^T), 8tok x 8j tiles,
    //      K software-pipelined in registers (double buffer) ----
    if (tid < 250) {
        u64 acc1[8][4];
        {
            u64 c0 = pack2(c_sh[jc],     c_sh[jc + 1]);
            u64 c1 = pack2(c_sh[jc + 2], c_sh[jc + 3]);
            u64 c2 = pack2(c_sh[jc + 4], c_sh[jc + 5]);
            u64 c3 = pack2(c_sh[jc + 6], c_sh[jc + 7]);
            #pragma unroll
            for (int tt = 0; tt < 8; tt++) {
                acc1[tt][0] = c0; acc1[tt][1] = c1; acc1[tt][2] = c2; acc1[tt][3] = c3;
            }
        }

        #pragma unroll 1
        for (int i = 0; i < DD - 2; i += 2) {
            // prefetch next i-pair while computing with kv
            float2 kn[8];
            #pragma unroll
            for (int tt = 0; tt < 8; tt++)
                kn[tt] = *(const float2*)(kb + tt * DD + i + 2);

            const ulonglong2* wr0 = (const ulonglong2*)(Wk + i * H1 + jc);
            const ulonglong2* wr1 = (const ulonglong2*)(Wk + (i + 1) * H1 + jc);
            ulonglong2 wA0 = wr0[0];
            ulonglong2 wB0 = wr0[1];
            ulonglong2 wA1 = wr1[0];
            ulonglong2 wB1 = wr1[1];
            #pragma unroll
            for (int tt = 0; tt < 8; tt++) {
                u64 s0 = pack2(kv[tt].x, kv[tt].x);
                u64 s1 = pack2(kv[tt].y, kv[tt].y);
                fma2(acc1[tt][0], s0, wA0.x);
                fma2(acc1[tt][1], s0, wA0.y);
                fma2(acc1[tt][2], s0, wB0.x);
                fma2(acc1[tt][3], s0, wB0.y);
                fma2(acc1[tt][0], s1, wA1.x);
                fma2(acc1[tt][1], s1, wA1.y);
                fma2(acc1[tt][2], s1, wB1.x);
                fma2(acc1[tt][3], s1, wB1.y);
            }
            #pragma unroll
            for (int tt = 0; tt < 8; tt++) kv[tt] = kn[tt];
        }
        {   // epilogue: last i-pair (i = 62)
            const int i = DD - 2;
            const ulonglong2* wr0 = (const ulonglong2*)(Wk + i * H1 + jc);
            const ulonglong2* wr1 = (const ulonglong2*)(Wk + (i + 1) * H1 + jc);
            ulonglong2 wA0 = wr0[0];
            ulonglong2 wB0 = wr0[1];
            ulonglong2 wA1 = wr1[0];
            ulonglong2 wB1 = wr1[1];
            #pragma unroll
            for (int tt = 0; tt < 8; tt++) {
                u64 s0 = pack2(kv[tt].x, kv[tt].x);
                u64 s1 = pack2(kv[tt].y, kv[tt].y);
                fma2(acc1[tt][0], s0, wA0.x);
                fma2(acc1[tt][1], s0, wA0.y);
                fma2(acc1[tt][2], s0, wB0.x);
                fma2(acc1[tt][3], s0, wB0.y);
                fma2(acc1[tt][0], s1, wA1.x);
                fma2(acc1[tt][1], s1, wA1.y);
                fma2(acc1[tt][2], s1, wB1.x);
                fma2(acc1[tt][3], s1, wB1.y);
            }
        }
        #pragma unroll
        for (int tt = 0; tt < 8; tt++)
            relu_store8(acc1[tt], S1 + (tg * 8 + tt) * S1S + jc);
    }
    __syncthreads();

    // ---- GEMM2: S2[200][40] = relu(b2 + S1 @ W2), 4tok x 8g tiles; fold Wf ----
    if (tid < 250) {
        const int tg2 = tid / 5;
        const int gg  = tid - tg2 * 5;
        const int gc  = gg * 8;
        const float* s1b = S1 + (size_t)(tg2 * 4) * S1S;

        u64 acc[4][4];
        {
            u64 c0 = pack2(b2s[gc],     b2s[gc + 1]);
            u64 c1 = pack2(b2s[gc + 2], b2s[gc + 3]);
            u64 c2 = pack2(b2s[gc + 4], b2s[gc + 5]);
            u64 c3 = pack2(b2s[gc + 6], b2s[gc + 7]);
            #pragma unroll
            for (int tt = 0; tt < 4; tt++) {
                acc[tt][0] = c0; acc[tt][1] = c1; acc[tt][2] = c2; acc[tt][3] = c3;
            }
        }

        #pragma unroll 2
        for (int j = 0; j < H1; j += 4) {
            float sr[4][4];
            *(float4*)sr[0] = *(const float4*)(s1b + 0 * S1S + j);
            *(float4*)sr[1] = *(const float4*)(s1b + 1 * S1S + j);
            *(float4*)sr[2] = *(const float4*)(s1b + 2 * S1S + j);
            *(float4*)sr[3] = *(const float4*)(s1b + 3 * S1S + j);
            #pragma unroll
            for (int ji = 0; ji < 4; ji++) {
                const ulonglong2* wr = (const ulonglong2*)(W2s + (j + ji) * H2 + gc);
                ulonglong2 wA = wr[0];
                ulonglong2 wB = wr[1];
                #pragma unroll
                for (int tt = 0; tt < 4; tt++) {
                    u64 s = pack2(sr[tt][ji], sr[tt][ji]);
                    fma2(acc[tt][0], s, wA.x);
                    fma2(acc[tt][1], s, wA.y);
                    fma2(acc[tt][2], s, wB.x);
                    fma2(acc[tt][3], s, wB.y);
                }
            }
        }
        float wf[8];
        *(float4*)wf       = *(const float4*)(Wfs + gc);
        *(float4*)(wf + 4) = *(const float4*)(Wfs + gc + 4);
        #pragma unroll
        for (int tt = 0; tt < 4; tt++)
            p2[(tg2 * 4 + tt) * 5 + gg] = relu_dot8(acc[tt], wf);
    }
    __syncthreads();

    // ---- score assembly + softmax ----
    if (tid < TT) {
        float s = bf[0] + ((p2[tid * 5] + p2[tid * 5 + 1]) +
                           (p2[tid * 5 + 2] + p2[tid * 5 + 3]) + p2[tid * 5 + 4]);
        if (mask[(size_t)b * TT + tid] == 0) s = NEG_BIG_F;
        sc[tid] = s;
    }
    __syncthreads();

    float mval = (tid < TT) ? sc[tid] : -3.0e38f;
    #pragma unroll
    for (int o = 16; o; o >>= 1)
        mval = fmaxf(mval, __shfl_xor_sync(0xffffffffu, mval, o));
    if ((tid & 31) == 0) red[tid >> 5] = mval;
    __syncthreads();
    if (tid == 0) {
        float m = red[0];
        #pragma unroll
        for (int w = 1; w < 8; w++) m = fmaxf(m, red[w]);
        mxin[0] = m;
    }
    __syncthreads();
    const float mx = mxin[0];
    float e = (tid < TT) ? __expf(sc[tid] - mx) : 0.0f;
    if (tid < TT) sc[tid] = e;
    float sval = e;
    #pragma unroll
    for (int o = 16; o; o >>= 1)
        sval += __shfl_xor_sync(0xffffffffu, sval, o);
    if ((tid & 31) == 0) red[tid >> 5] = sval;
    __syncthreads();
    if (tid == 0) {
        float smv = 0.0f;
        #pragma unroll
        for (int w = 0; w < 8; w++) smv += red[w];
        mxin[1] = 1.0f / smv;
    }
    __syncthreads();

    // ---- out = attn @ V ----
    const float inv = mxin[1];
    const int dd = tid & 63;
    const int p  = tid >> 6;
    const float* vb = v + (size_t)b * TT * DD;
    float a0 = 0.f, a1 = 0.f;
    const int t0 = p * 50;
    #pragma unroll 5
    for (int t = t0; t < t0 + 50; t += 2) {
        a0 = fmaf(sc[t],     vb[(size_t)t * DD + dd],       a0);
        a1 = fmaf(sc[t + 1], vb[(size_t)(t + 1) * DD + dd], a1);
    }
    part[tid] = a0 + a1;
    __syncthreads();
    if (tid < DD) {
        float r = part[tid] + part[tid + 64] + part[tid + 128] + part[tid + 192];
        out[(size_t)b * DD + tid] = r * inv;
    }
}

extern "C" void kernel_launch(void* const* d_in, const int* in_sizes, int n_in,
                              void* d_out, int out_size)
{
    const float* q    = (const float*)d_in[0];
    const float* k    = (const float*)d_in[1];
    const float* v    = (const float*)d_in[2];
    const int*   mask = (const int*)  d_in[3];
    const float* W1   = (const float*)d_in[4];
    const float* b1   = (const float*)d_in[5];
    const float* W2   = (const float*)d_in[6];
    const float* b2   = (const float*)d_in[7];
    const float* Wf   = (const float*)d_in[8];
    const float* bf   = (const float*)d_in[9];
    float* out = (float*)d_out;

    const int smem_bytes = SMEM_FLOATS * (int)sizeof(float);
    cudaFuncSetAttribute(din_attn_kernel,
                         cudaFuncAttributeMaxDynamicSharedMemorySize, smem_bytes);
    din_attn_kernel<<<BB, 256, smem_bytes>>>(q, k, v, mask, W1, b1, W2, b2, Wf, bf, out);
}